// round 3
// baseline (speedup 1.0000x reference)
#include <cuda_runtime.h>
#include <cuda_fp16.h>
#include <cstdint>

// ===================== problem sizes =====================
static constexpr int  B_   = 8192;
static constexpr int  C_   = 12;
static constexpr int  A_   = 8;
static constexpr int  DI   = 1024;
static constexpr int  DO   = 1024;
static constexpr int  NTOT = C_ * DO;        // 12288
static constexpr int  KE   = 3 * DI;         // 3072 (expanded K: hh+hl+lh split)
static constexpr long NX   = (long)B_ * DI;      // 8388608
static constexpr long NW   = (long)NTOT * DI;    // 12582912

// ===================== device scratch (no allocs allowed) ====================
__device__ __half g_xe[(size_t)B_ * KE];     // 50 MB  a = [xh, xh, xl]
__device__ __half g_we[(size_t)NTOT * KE];   // 75 MB  b = [wh, wl, wh]
__device__ float  g_u[(size_t)B_ * NTOT];    // 402 MB u = x@W^T + bias
__device__ float  g_ent[B_];

// ===================== helpers =====================
__device__ __forceinline__ uint32_t smem_u32(const void* p) {
    uint32_t a;
    asm("{ .reg .u64 t; cvta.to.shared.u64 t, %1; cvt.u32.u64 %0, t; }" : "=r"(a) : "l"(p));
    return a;
}
__device__ __forceinline__ void cp_async16(uint32_t smem_dst, const void* gsrc) {
    asm volatile("cp.async.cg.shared.global [%0], [%1], 16;" :: "r"(smem_dst), "l"(gsrc));
}
#define CP_COMMIT() asm volatile("cp.async.commit_group;" ::: "memory")
#define CP_WAIT(n)  asm volatile("cp.async.wait_group %0;" :: "n"(n) : "memory")

#define LDSM_X4(R0,R1,R2,R3,ADDR) \
    asm volatile("ldmatrix.sync.aligned.m8n8.x4.shared.b16 {%0,%1,%2,%3}, [%4];" \
                 : "=r"(R0),"=r"(R1),"=r"(R2),"=r"(R3) : "r"(ADDR))

#define MMA16816(C0,C1,C2,C3,A0,A1,A2,A3,B0,B1) \
    asm volatile("mma.sync.aligned.m16n8k16.row.col.f32.f16.f16.f32 " \
                 "{%0,%1,%2,%3}, {%4,%5,%6,%7}, {%8,%9}, {%0,%1,%2,%3};" \
                 : "+f"(C0),"+f"(C1),"+f"(C2),"+f"(C3) \
                 : "r"(A0),"r"(A1),"r"(A2),"r"(A3),"r"(B0),"r"(B1))

// ===================== kernel 1: fp16 split + K-expansion =====================
__global__ __launch_bounds__(256) void split_kernel(const float* __restrict__ x,
                                                    const float* __restrict__ W) {
    long i = (long)blockIdx.x * 256 + threadIdx.x;
    if (i < NX) {
        long b = i >> 10, k = i & 1023;
        float v = x[i];
        __half h = __float2half_rn(v);
        __half l = __float2half_rn(v - __half2float(h));
        size_t base = (size_t)b * KE;
        g_xe[base + k]        = h;
        g_xe[base + 1024 + k] = h;
        g_xe[base + 2048 + k] = l;
    } else {
        long j = i - NX;
        if (j < NW) {
            long n = j >> 10, k = j & 1023;
            float v = W[j];
            __half h = __float2half_rn(v);
            __half l = __float2half_rn(v - __half2float(h));
            size_t base = (size_t)n * KE;
            g_we[base + k]        = h;
            g_we[base + 1024 + k] = l;
            g_we[base + 2048 + k] = h;
        }
    }
}

// ===================== kernel 2: HMMA GEMM  u = x @ W^T + bias =================
// CTA 128x256, 8 warps (2m x 4n) of 64x64, TK=32 fp16, 4-stage cp.async pipeline.
// smem rows padded to 80B (5x16B) -> conflict-free ldmatrix without XOR swizzle.
static constexpr int TM = 128, TN = 256, TK = 32, STAGES = 4;
static constexpr int ROWB = 80;
static constexpr int ASTG = TM * ROWB;            // 10240
static constexpr int BSTG = TN * ROWB;            // 20480
static constexpr int STG  = ASTG + BSTG;          // 30720
static constexpr int GEMM_SMEM = STAGES * STG;    // 122880
static constexpr int KITERS = KE / TK;            // 96

__global__ __launch_bounds__(256, 1) void gemm_kernel(const float* __restrict__ bias) {
    extern __shared__ char sm[];
    const uint32_t sb = smem_u32(sm);
    const int tid  = threadIdx.x;
    const int lane = tid & 31;
    const int w    = tid >> 5;
    const int wm   = w & 1;          // 2 warps along M (64 each)
    const int wn   = w >> 1;         // 4 warps along N (64 each)
    const long m0  = (long)blockIdx.y * TM;
    const long n0  = (long)blockIdx.x * TN;

    float acc[4][8][4];
    #pragma unroll
    for (int mt = 0; mt < 4; mt++)
        #pragma unroll
        for (int nt = 0; nt < 8; nt++)
            #pragma unroll
            for (int e = 0; e < 4; e++) acc[mt][nt][e] = 0.f;

    // per-thread load granules: A 512 (2/thread), B 1024 (4/thread)
    const int ar0 = tid >> 2,        ac0 = tid & 3;        // +64 rows per q
    // ldmatrix per-lane bases
    const uint32_t rowA = (uint32_t)(wm * 64 + (lane & 7) + ((lane >> 3) & 1) * 8);
    const uint32_t colA = (uint32_t)(((lane >> 4) & 1) * 16);
    const uint32_t rowB = (uint32_t)(wn * 64 + (lane & 7) + ((lane >> 4) & 1) * 8);
    const uint32_t colB = (uint32_t)(((lane >> 3) & 1) * 16);

    auto load_stage = [&](int j) {
        const uint32_t As = sb + (uint32_t)((j & 3) * STG);
        const uint32_t Bs = As + ASTG;
        const long k0 = (long)j * TK;
        #pragma unroll
        for (int q = 0; q < 2; q++) {
            int r = ar0 + q * 64, c = ac0;
            cp_async16(As + r * ROWB + c * 16, &g_xe[(size_t)(m0 + r) * KE + k0 + c * 8]);
        }
        #pragma unroll
        for (int q = 0; q < 4; q++) {
            int r = ar0 + q * 64, c = ac0;
            cp_async16(Bs + r * ROWB + c * 16, &g_we[(size_t)(n0 + r) * KE + k0 + c * 8]);
        }
    };

    // prologue: stages 0..2
    #pragma unroll
    for (int j = 0; j < STAGES - 1; j++) { load_stage(j); CP_COMMIT(); }

    #pragma unroll 1
    for (int i = 0; i < KITERS; i++) {
        CP_WAIT(STAGES - 2);
        __syncthreads();
        if (i + STAGES - 1 < KITERS) load_stage(i + STAGES - 1);
        CP_COMMIT();

        const uint32_t As = sb + (uint32_t)((i & 3) * STG);
        const uint32_t Bs = As + ASTG;
        #pragma unroll
        for (int ks = 0; ks < 2; ks++) {
            uint32_t a[4][4], b[8][2];
            #pragma unroll
            for (int mt = 0; mt < 4; mt++) {
                uint32_t ad = As + (rowA + mt * 16) * ROWB + ks * 32 + colA;
                LDSM_X4(a[mt][0], a[mt][1], a[mt][2], a[mt][3], ad);
            }
            #pragma unroll
            for (int p = 0; p < 4; p++) {
                uint32_t bd = Bs + (rowB + p * 16) * ROWB + ks * 32 + colB;
                LDSM_X4(b[2*p][0], b[2*p][1], b[2*p+1][0], b[2*p+1][1], bd);
            }
            #pragma unroll
            for (int mt = 0; mt < 4; mt++)
                #pragma unroll
                for (int nt = 0; nt < 8; nt++)
                    MMA16816(acc[mt][nt][0], acc[mt][nt][1], acc[mt][nt][2], acc[mt][nt][3],
                             a[mt][0], a[mt][1], a[mt][2], a[mt][3],
                             b[nt][0], b[nt][1]);
        }
    }

    // epilogue: add bias, store fp32 to g_u (float2 per fragment row)
    #pragma unroll
    for (int nt = 0; nt < 8; nt++) {
        const long n = n0 + wn * 64 + nt * 8 + 2 * (lane & 3);
        const float2 bz = *(const float2*)&bias[n];
        #pragma unroll
        for (int mt = 0; mt < 4; mt++) {
            const long m = m0 + wm * 64 + mt * 16 + (lane >> 2);
            float2 lo = { acc[mt][nt][0] + bz.x, acc[mt][nt][1] + bz.y };
            float2 hi = { acc[mt][nt][2] + bz.x, acc[mt][nt][3] + bz.y };
            *(float2*)&g_u[(size_t)m * NTOT + n]       = lo;
            *(float2*)&g_u[(size_t)(m + 8) * NTOT + n] = hi;
        }
    }
}

// ===================== kernel 3: fused routing =====================
__device__ __forceinline__ float block_sum(float v, volatile float* smr) {
    int lane = threadIdx.x & 31, w = threadIdx.x >> 5;
    #pragma unroll
    for (int o = 16; o; o >>= 1) v += __shfl_xor_sync(0xffffffffu, v, o);
    if (lane == 0) smr[w] = v;
    __syncthreads();
    if (threadIdx.x == 0) {
        float s = smr[0];
        #pragma unroll
        for (int i = 1; i < 8; i++) s += smr[i];
        smr[8] = s;
    }
    __syncthreads();
    float r = smr[8];
    __syncthreads();
    return r;
}
__device__ __forceinline__ float block_max(float v, volatile float* smr) {
    int lane = threadIdx.x & 31, w = threadIdx.x >> 5;
    #pragma unroll
    for (int o = 16; o; o >>= 1) v = fmaxf(v, __shfl_xor_sync(0xffffffffu, v, o));
    if (lane == 0) smr[w] = v;
    __syncthreads();
    if (threadIdx.x == 0) {
        float s = smr[0];
        #pragma unroll
        for (int i = 1; i < 8; i++) s = fmaxf(s, smr[i]);
        smr[8] = s;
    }
    __syncthreads();
    float r = smr[8];
    __syncthreads();
    return r;
}

__global__ __launch_bounds__(256) void routing_kernel(float* __restrict__ out) {
    __shared__ float sred[9];
    __shared__ float s12[8 * 12];
    __shared__ float sb12[12];
    const int b = blockIdx.x;
    const int t = threadIdx.x;
    const int lid = t & 31, wid = t >> 5;

    float ur[12][4];
    const float* ub = g_u + (size_t)b * NTOT;
    #pragma unroll
    for (int c = 0; c < 12; c++)
        #pragma unroll
        for (int j = 0; j < 4; j++)
            ur[c][j] = ub[c * 1024 + t + 256 * j];

    float blog[12];
    #pragma unroll
    for (int c = 0; c < 12; c++) blog[c] = 0.f;

    float s[4], v[4];
    for (int it = 0; it < 3; it++) {
        float mx = blog[0];
        #pragma unroll
        for (int c = 1; c < 12; c++) mx = fmaxf(mx, blog[c]);
        float cc[12], se = 0.f;
        #pragma unroll
        for (int c = 0; c < 12; c++) { cc[c] = expf(blog[c] - mx); se += cc[c]; }
        const float inv = 1.f / se;
        #pragma unroll
        for (int j = 0; j < 4; j++) s[j] = 0.f;
        #pragma unroll
        for (int c = 0; c < 12; c++) {
            float wgt = cc[c] * inv;
            #pragma unroll
            for (int j = 0; j < 4; j++) s[j] = fmaf(wgt, ur[c][j], s[j]);
        }
        float n2p = s[0]*s[0] + s[1]*s[1] + s[2]*s[2] + s[3]*s[3];
        float n2 = block_sum(n2p, sred);
        float nrm = sqrtf(n2);
        float scale = n2 / (1.f + n2) / (nrm + 1e-8f);
        #pragma unroll
        for (int j = 0; j < 4; j++) v[j] = scale * s[j];
        if (it < 2) {
            #pragma unroll
            for (int c = 0; c < 12; c++) {
                float p = ur[c][0]*v[0] + ur[c][1]*v[1] + ur[c][2]*v[2] + ur[c][3]*v[3];
                #pragma unroll
                for (int o = 16; o; o >>= 1) p += __shfl_xor_sync(0xffffffffu, p, o);
                if (lid == 0) s12[wid * 12 + c] = p;
            }
            __syncthreads();
            if (t < 12) {
                float a2 = 0.f;
                #pragma unroll
                for (int w2 = 0; w2 < 8; w2++) a2 += s12[w2 * 12 + t];
                sb12[t] = a2;
            }
            __syncthreads();
            #pragma unroll
            for (int c = 0; c < 12; c++) blog[c] += sb12[c];
            __syncthreads();
        }
    }

    // v replicated across A=8 heads
    size_t ob = (size_t)b * (A_ * DO);
    #pragma unroll
    for (int a = 0; a < A_; a++)
        #pragma unroll
        for (int j = 0; j < 4; j++)
            out[ob + (size_t)a * DO + t + 256 * j] = v[j];

    // entropy over final (unsquashed) s
    float mxp = fmaxf(fmaxf(s[0], s[1]), fmaxf(s[2], s[3]));
    float mxs = block_max(mxp, sred);
    float sep = expf(s[0]-mxs) + expf(s[1]-mxs) + expf(s[2]-mxs) + expf(s[3]-mxs);
    float sume = block_sum(sep, sred);
    float denom = sume + 1e-10f;
    float ep = 0.f;
    #pragma unroll
    for (int j = 0; j < 4; j++) {
        float pj = expf(s[j] - mxs) / denom;
        ep += pj * logf(pj + 1e-10f);
    }
    float H = -block_sum(ep, sred);
    H = fminf(fmaxf(H, 0.f), 10.f);
    if (t == 0) g_ent[b] = H;
}

// ===================== kernel 4: entropy loss scalar =====================
__global__ __launch_bounds__(256) void finalize_kernel(float* __restrict__ out, long idx) {
    __shared__ float sred[9];
    const int t = threadIdx.x;
    float sum = 0.f;
    for (int k = t; k < B_; k += 256) sum += g_ent[k];
    float total = block_sum(sum, sred);
    if (t == 0) {
        float mean = total / (float)B_;
        out[idx] = -0.4f / (1.f + expf(-mean));
    }
}

// ===================== launch =====================
extern "C" void kernel_launch(void* const* d_in, const int* in_sizes, int n_in,
                              void* d_out, int out_size) {
    const float* x    = (const float*)d_in[0];
    const float* W    = (const float*)d_in[1];
    const float* bias = (const float*)d_in[2];
    float* out = (float*)d_out;

    long total = NX + NW;
    split_kernel<<<(int)((total + 255) / 256), 256>>>(x, W);

    (void)cudaFuncSetAttribute(gemm_kernel, cudaFuncAttributeMaxDynamicSharedMemorySize, GEMM_SMEM);
    dim3 ggrid(NTOT / TN, B_ / TM);   // (48, 64)
    gemm_kernel<<<ggrid, 256, GEMM_SMEM>>>(bias);

    routing_kernel<<<B_, 256>>>(out);
    finalize_kernel<<<1, 256>>>(out, (long)out_size - 1);
}